// round 11
// baseline (speedup 1.0000x reference)
#include <cuda_runtime.h>
#include <cuda_bf16.h>
#include <math.h>
#include <stdint.h>

#define BB  2
#define TT  8192
#define EE  256
#define CSZ 128
#define NCH 64      // TT / CSZ
#define KT  8       // K slots (7 retrieved + current)

// ---- scratch (device globals; no allocation allowed) ----
__device__ __nv_bfloat16 g_hi[(size_t)BB * TT * EE];   // bf16 hi of normalized rows
__device__ __nv_bfloat16 g_lo[(size_t)BB * TT * EE];   // bf16 residual (normalized)
__device__ __nv_bfloat16 g_xh[(size_t)BB * TT * EE];   // bf16 hi of raw x
__device__ __nv_bfloat16 g_xl[(size_t)BB * TT * EE];   // bf16 residual of raw x
__device__ float g_scores[BB * NCH * NCH];
__device__ int   g_src[BB * NCH * KT];
__device__ float g_wgt[BB * NCH * KT];

// ================= helpers =================
__device__ __forceinline__ uint32_t smem_u32(const void* p) {
    uint32_t a;
    asm("{ .reg .u64 t; cvta.to.shared.u64 t, %1; cvt.u32.u64 %0, t; }" : "=r"(a) : "l"(p));
    return a;
}
__device__ __forceinline__ void cp_async16(uint32_t dst, const void* src) {
    asm volatile("cp.async.cg.shared.global [%0], [%1], 16;" :: "r"(dst), "l"(src));
}
#define CP_ASYNC_COMMIT() asm volatile("cp.async.commit_group;" ::: "memory")
#define CP_ASYNC_WAIT1()  asm volatile("cp.async.wait_group 1;"  ::: "memory")
#define CP_ASYNC_WAIT0()  asm volatile("cp.async.wait_group 0;"  ::: "memory")
#define LDSM_X4(R, a) \
    asm volatile("ldmatrix.sync.aligned.m8n8.x4.shared.b16 {%0,%1,%2,%3}, [%4];" \
        : "=r"((R)[0]), "=r"((R)[1]), "=r"((R)[2]), "=r"((R)[3]) : "r"(a))
#define LDSM_X4_T(R, a) \
    asm volatile("ldmatrix.sync.aligned.m8n8.x4.trans.shared.b16 {%0,%1,%2,%3}, [%4];" \
        : "=r"((R)[0]), "=r"((R)[1]), "=r"((R)[2]), "=r"((R)[3]) : "r"(a))
#define MMA16816(D, A, B0, B1) \
    asm volatile("mma.sync.aligned.m16n8k16.row.col.f32.bf16.bf16.f32 " \
        "{%0,%1,%2,%3}, {%4,%5,%6,%7}, {%8,%9}, {%0,%1,%2,%3};" \
        : "+f"((D)[0]), "+f"((D)[1]), "+f"((D)[2]), "+f"((D)[3]) \
        : "r"((A)[0]), "r"((A)[1]), "r"((A)[2]), "r"((A)[3]), "r"(B0), "r"(B1))

// ============================================================
// 1) Row normalization -> bf16 hi/lo of cn, plus bf16 hi/lo of raw x
// ============================================================
__global__ void normalize_k(const float* __restrict__ x) {
    int row  = blockIdx.x * 8 + (threadIdx.x >> 5);
    int lane = threadIdx.x & 31;
    const float4* xr = (const float4*)(x + (size_t)row * EE);
    float4 v0 = xr[lane];
    float4 v1 = xr[lane + 32];
    float ss = v0.x*v0.x + v0.y*v0.y + v0.z*v0.z + v0.w*v0.w
             + v1.x*v1.x + v1.y*v1.y + v1.z*v1.z + v1.w*v1.w;
    #pragma unroll
    for (int o = 16; o > 0; o >>= 1) ss += __shfl_xor_sync(0xffffffffu, ss, o);
    float inv = 1.0f / (sqrtf(ss) + 1e-6f);

    float fr[8] = { v0.x, v0.y, v0.z, v0.w, v1.x, v1.y, v1.z, v1.w };
    size_t base = (size_t)row * EE;
    uint32_t* hp = (uint32_t*)(g_hi + base);
    uint32_t* lp = (uint32_t*)(g_lo + base);
    uint32_t* xhp = (uint32_t*)(g_xh + base);
    uint32_t* xlp = (uint32_t*)(g_xl + base);

    __nv_bfloat16 h[8], l[8], rh[8], rl[8];
    #pragma unroll
    for (int t = 0; t < 8; t++) {
        float fn = fr[t] * inv;
        h[t]  = __float2bfloat16(fn);
        l[t]  = __float2bfloat16(fn - __bfloat162float(h[t]));
        rh[t] = __float2bfloat16(fr[t]);
        rl[t] = __float2bfloat16(fr[t] - __bfloat162float(rh[t]));
    }
    #pragma unroll
    for (int t = 0; t < 2; t++) {
        int eb = t * 64 + lane * 2;
        __nv_bfloat162 a0(h[t*4+0], h[t*4+1]),  a1(h[t*4+2], h[t*4+3]);
        __nv_bfloat162 b0(l[t*4+0], l[t*4+1]),  b1(l[t*4+2], l[t*4+3]);
        __nv_bfloat162 c0(rh[t*4+0], rh[t*4+1]), c1(rh[t*4+2], rh[t*4+3]);
        __nv_bfloat162 d0(rl[t*4+0], rl[t*4+1]), d1(rl[t*4+2], rl[t*4+3]);
        hp[eb]  = *(uint32_t*)&a0;  hp[eb+1]  = *(uint32_t*)&a1;
        lp[eb]  = *(uint32_t*)&b0;  lp[eb+1]  = *(uint32_t*)&b1;
        xhp[eb] = *(uint32_t*)&c0;  xhp[eb+1] = *(uint32_t*)&c1;
        xlp[eb] = *(uint32_t*)&d0;  xlp[eb+1] = *(uint32_t*)&d1;
    }
}

// ============================================================
// 2) Score kernel via mma.sync bf16x3, cp.async double-buffered.
//    One CTA (8 warps) per (b,i,j), j<i.
//    D = Ah·Bh^T + Ah·Bl^T + Al·Bh^T ; score = sum_c max_d D[c][d]
// smem: 2 stages x (4 tiles x 16KB) = 128KB, + red/wsum
// ============================================================
__global__ void __launch_bounds__(256, 1)
score_hmma_k() {
    int j = blockIdx.x, i = blockIdx.y, b = blockIdx.z;
    if (j >= i) return;

    extern __shared__ char smem[];
    uint32_t sb = smem_u32(smem);
    const uint32_t TSZ  = 16384;
    const uint32_t SSTG = 65536;    // stage stride (4 tiles)
    float* red  = (float*)(smem + 2 * SSTG);           // [128][2]
    float* wsum = (float*)(smem + 2 * SSTG + 1024);    // [8]

    int tid  = threadIdx.x;
    int wid  = tid >> 5;
    int lane = tid & 31;
    int wr = wid >> 1;
    int wc = wid & 1;

    const __nv_bfloat16* srcp[4] = {
        g_hi + ((size_t)(b * NCH + i) * CSZ) * EE,
        g_lo + ((size_t)(b * NCH + i) * CSZ) * EE,
        g_hi + ((size_t)(b * NCH + j) * CSZ) * EE,
        g_lo + ((size_t)(b * NCH + j) * CSZ) * EE
    };

    auto issue_stage = [&](int c, int stg) {
        int k0 = c * 64;
        #pragma unroll
        for (int t = 0; t < 4; t++) {
            const __nv_bfloat16* s = srcp[t] + k0;
            uint32_t tb = sb + stg * SSTG + t * TSZ;
            #pragma unroll
            for (int q = 0; q < 4; q++) {
                int idx = q * 256 + tid;
                int r   = idx >> 3;
                int c8  = idx & 7;
                cp_async16(tb + (uint32_t)(r * 128 + ((c8 ^ (r & 7)) << 4)),
                           s + (size_t)r * EE + c8 * 8);
            }
        }
        CP_ASYNC_COMMIT();
    };

    float acc[2][8][4];
    #pragma unroll
    for (int mt = 0; mt < 2; mt++)
        #pragma unroll
        for (int nt = 0; nt < 8; nt++)
            #pragma unroll
            for (int e = 0; e < 4; e++) acc[mt][nt][e] = 0.0f;

    int a_r = (lane & 15);
    int a_c = (lane >> 4);
    int b_r = (lane & 7) + ((lane >> 4) << 3);
    int b_c = (lane >> 3) & 1;

    issue_stage(0, 0);
    issue_stage(1, 1);

    for (int c = 0; c < 4; c++) {
        if (c < 3) { CP_ASYNC_WAIT1(); } else { CP_ASYNC_WAIT0(); }
        __syncthreads();
        uint32_t sg = sb + (uint32_t)(c & 1) * SSTG;

        #pragma unroll
        for (int kk = 0; kk < 4; kk++) {
            uint32_t ahi[2][4], alo[2][4];
            #pragma unroll
            for (int mt = 0; mt < 2; mt++) {
                int r   = wr * 32 + mt * 16 + a_r;
                int c16 = kk * 2 + a_c;
                uint32_t off = (uint32_t)(r * 128 + ((c16 ^ (r & 7)) << 4));
                LDSM_X4(ahi[mt], sg + 0 * TSZ + off);
                LDSM_X4(alo[mt], sg + 1 * TSZ + off);
            }
            #pragma unroll
            for (int np = 0; np < 4; np++) {
                int r   = wc * 64 + np * 16 + b_r;
                int c16 = kk * 2 + b_c;
                uint32_t off = (uint32_t)(r * 128 + ((c16 ^ (r & 7)) << 4));
                uint32_t bh[4], bl[4];
                LDSM_X4(bh, sg + 2 * TSZ + off);
                LDSM_X4(bl, sg + 3 * TSZ + off);
                #pragma unroll
                for (int mt = 0; mt < 2; mt++) {
                    #pragma unroll
                    for (int h = 0; h < 2; h++) {
                        float* D = acc[mt][np * 2 + h];
                        MMA16816(D, ahi[mt], bh[h*2], bh[h*2+1]);
                        MMA16816(D, ahi[mt], bl[h*2], bl[h*2+1]);
                        MMA16816(D, alo[mt], bh[h*2], bh[h*2+1]);
                    }
                }
            }
        }
        __syncthreads();
        if (c + 2 < 4) issue_stage(c + 2, c & 1);
    }

    float mx[4];
    #pragma unroll
    for (int mt = 0; mt < 2; mt++) {
        float m0 = -3.0e38f, m1 = -3.0e38f;
        #pragma unroll
        for (int nt = 0; nt < 8; nt++) {
            m0 = fmaxf(m0, fmaxf(acc[mt][nt][0], acc[mt][nt][1]));
            m1 = fmaxf(m1, fmaxf(acc[mt][nt][2], acc[mt][nt][3]));
        }
        mx[mt * 2 + 0] = m0;
        mx[mt * 2 + 1] = m1;
    }
    #pragma unroll
    for (int o = 1; o <= 2; o <<= 1) {
        #pragma unroll
        for (int s = 0; s < 4; s++)
            mx[s] = fmaxf(mx[s], __shfl_xor_sync(0xffffffffu, mx[s], o));
    }
    if ((lane & 3) == 0) {
        int r = lane >> 2;
        #pragma unroll
        for (int s = 0; s < 4; s++) {
            int row = wr * 32 + (s >> 1) * 16 + (s & 1) * 8 + r;
            red[row * 2 + wc] = mx[s];
        }
    }
    __syncthreads();

    float total = 0.0f;
    if (tid < 128)
        total = fmaxf(red[tid * 2], red[tid * 2 + 1]);
    #pragma unroll
    for (int o = 16; o > 0; o >>= 1) total += __shfl_xor_sync(0xffffffffu, total, o);
    if (tid < 128 && lane == 0) wsum[wid] = total;
    __syncthreads();
    if (tid == 0)
        g_scores[(b * NCH + i) * NCH + j] = wsum[0] + wsum[1] + wsum[2] + wsum[3];
}

// ============================================================
// 3) Top-(K-1) selection, warp-parallel per (b,i).
// ============================================================
__global__ void topk_warp_k() {
    int i = blockIdx.x, b = blockIdx.y;
    int lane = threadIdx.x;
    const float* srow = g_scores + (b * NCH + i) * NCH;

    int num_sel = i < 7 ? i : 7;
    int shift   = 7 - num_sel;

    float v0 = (lane      < i) ? srow[lane]      : -3.0e38f;
    float v1 = (lane + 32 < i) ? srow[lane + 32] : -3.0e38f;

    float vals[7];
    int   idxs[7];
    for (int r = 0; r < num_sel; r++) {
        float mv = v0; int mi = lane;
        if (v1 > mv) { mv = v1; mi = lane + 32; }
        #pragma unroll
        for (int o = 16; o > 0; o >>= 1) {
            float ov = __shfl_xor_sync(0xffffffffu, mv, o);
            int   oi = __shfl_xor_sync(0xffffffffu, mi, o);
            if (ov > mv || (ov == mv && oi < mi)) { mv = ov; mi = oi; }
        }
        vals[r] = mv; idxs[r] = mi;
        if (mi == lane)      v0 = -3.0e38f;
        if (mi == lane + 32) v1 = -3.0e38f;
    }

    if (lane == 0) {
        float vmin = (num_sel > 0) ? vals[num_sel - 1] : 0.0f;
        int base = (b * NCH + i) * KT;
        for (int slot = 0; slot < 7; slot++) {
            if (slot >= shift) {
                int r = slot - shift;
                g_src[base + slot] = idxs[r];
                g_wgt[base + slot] = vals[r] / (vmin + 1e-6f);
            } else {
                g_src[base + slot] = i;
                g_wgt[base + slot] = 0.0f;
            }
        }
        g_src[base + 7] = i;
        g_wgt[base + 7] = 1.0f;
    }
}

// ============================================================
// 4) Output GEMM via mma.sync bf16x3, cp.async double-buffered
//    over the (slot,kc) stage sequence. One CTA (8 warps) per (b,i).
//    C[128,256] = sum_s (w_s·dp[:, s*128:+128]) @ x[b,src_s] + x_chunk
// smem: 2 stages x (AH 16K | AL 16K | BH 32K | BL 32K) = 192KB
// ============================================================
__global__ void __launch_bounds__(256, 1)
out_hmma_k(const float* __restrict__ x, const float* __restrict__ dp,
           float* __restrict__ out) {
    int i = blockIdx.x, b = blockIdx.y;

    extern __shared__ char smem[];
    uint32_t sb = smem_u32(smem);
    const uint32_t AH = 0, AL = 16384, BH = 32768, BL = 65536;
    const uint32_t OSTG = 98304;   // stage stride (96KB)

    __shared__ int   s_src[KT];
    __shared__ float s_w[KT];

    int tid  = threadIdx.x;
    int wid  = tid >> 5;
    int lane = tid & 31;
    int wr = wid >> 2;      // 0..1 : rows [wr*64, +64)
    int wc = wid & 3;       // 0..3 : cols [wc*64, +64)

    if (tid < KT) {
        s_src[tid] = g_src[(b * NCH + i) * KT + tid];
        s_w[tid]   = g_wgt[(b * NCH + i) * KT + tid];
    }
    __syncthreads();

    int shift = (i < 7) ? (7 - i) : 0;
    int nst   = 2 * (8 - shift);    // stages: (slot,kc), slot=shift..7

    // fill stage t into buffer stg: B via cp.async (1 commit group), A converted
    auto fill = [&](int t, int stg) {
        int s  = shift + (t >> 1);
        int kc = t & 1;
        uint32_t base = sb + (uint32_t)stg * OSTG;
        // B tiles (bf16 hi/lo of raw x), async
        {
            size_t rb = ((size_t)b * TT + (size_t)s_src[s] * CSZ + kc * 64) * EE;
            const __nv_bfloat16* xbh = g_xh + rb;
            const __nv_bfloat16* xbl = g_xl + rb;
            #pragma unroll
            for (int q = 0; q < 8; q++) {
                int idx = q * 256 + tid;   // 0..2047 granules
                int k   = idx >> 5;
                int g   = idx & 31;
                uint32_t dst = (uint32_t)(k * 512 + ((g ^ (k & 7)) << 4));
                cp_async16(base + BH + dst, xbh + (size_t)k * EE + g * 8);
                cp_async16(base + BL + dst, xbl + (size_t)k * EE + g * 8);
            }
            CP_ASYNC_COMMIT();
        }
        // A tile: w * dp, converted to hi/lo (synchronous stores)
        {
            float w = s_w[s];
            int col0 = s * 128 + kc * 64;
            char* bp = smem + (size_t)stg * OSTG;
            #pragma unroll
            for (int q = 0; q < 4; q++) {
                int idx = q * 256 + tid;   // 0..1023 granules
                int r   = idx >> 3;
                int gk  = idx & 7;
                const float* dps = dp + (size_t)r * 1024 + col0 + gk * 8;
                float4 u0 = *(const float4*)(dps);
                float4 u1 = *(const float4*)(dps + 4);
                float f[8] = { w*u0.x, w*u0.y, w*u0.z, w*u0.w,
                               w*u1.x, w*u1.y, w*u1.z, w*u1.w };
                __nv_bfloat16 h[8], l[8];
                #pragma unroll
                for (int t2 = 0; t2 < 8; t2++) {
                    h[t2] = __float2bfloat16(f[t2]);
                    l[t2] = __float2bfloat16(f[t2] - __bfloat162float(h[t2]));
                }
                __nv_bfloat162 hh[4] = { {h[0],h[1]}, {h[2],h[3]}, {h[4],h[5]}, {h[6],h[7]} };
                __nv_bfloat162 ll[4] = { {l[0],l[1]}, {l[2],l[3]}, {l[4],l[5]}, {l[6],l[7]} };
                uint32_t dst = (uint32_t)(r * 128 + ((gk ^ (r & 7)) << 4));
                *(uint4*)(bp + AH + dst) = *(uint4*)hh;
                *(uint4*)(bp + AL + dst) = *(uint4*)ll;
            }
        }
    };

    float acc[4][8][4];
    #pragma unroll
    for (int mt = 0; mt < 4; mt++)
        #pragma unroll
        for (int nt = 0; nt < 8; nt++)
            #pragma unroll
            for (int e = 0; e < 4; e++) acc[mt][nt][e] = 0.0f;

    int a_r = (lane & 15);
    int a_c = (lane >> 4);
    int b_k = (lane & 7) + (((lane >> 3) & 1) << 3);
    int b_g = (lane >> 4);

    fill(0, 0);
    fill(1, 1);

    for (int t = 0; t < nst; t++) {
        if (t < nst - 1) { CP_ASYNC_WAIT1(); } else { CP_ASYNC_WAIT0(); }
        __syncthreads();
        uint32_t sg = sb + (uint32_t)(t & 1) * OSTG;

        #pragma unroll
        for (int kk = 0; kk < 4; kk++) {
            uint32_t ahi[4][4], alo[4][4];
            #pragma unroll
            for (int mt = 0; mt < 4; mt++) {
                int r   = wr * 64 + mt * 16 + a_r;
                int c16 = kk * 2 + a_c;
                uint32_t off = (uint32_t)(r * 128 + ((c16 ^ (r & 7)) << 4));
                LDSM_X4(ahi[mt], sg + AH + off);
                LDSM_X4(alo[mt], sg + AL + off);
            }
            #pragma unroll
            for (int np = 0; np < 4; np++) {
                int k = kk * 16 + b_k;
                int g = (wc * 8 + np * 2) + b_g;
                uint32_t off = (uint32_t)(k * 512 + ((g ^ (k & 7)) << 4));
                uint32_t bh[4], bl[4];
                LDSM_X4_T(bh, sg + BH + off);
                LDSM_X4_T(bl, sg + BL + off);
                #pragma unroll
                for (int mt = 0; mt < 4; mt++) {
                    #pragma unroll
                    for (int h = 0; h < 2; h++) {
                        float* D = acc[mt][np * 2 + h];
                        MMA16816(D, ahi[mt], bh[h*2], bh[h*2+1]);
                        MMA16816(D, ahi[mt], bl[h*2], bl[h*2+1]);
                        MMA16816(D, alo[mt], bh[h*2], bh[h*2+1]);
                    }
                }
            }
        }
        __syncthreads();
        if (t + 2 < nst) fill(t + 2, t & 1);
    }

    // ---- epilogue: += residual x chunk, store ----
    size_t obase = ((size_t)b * TT + (size_t)i * CSZ) * EE;
    int qr = lane >> 2, qc = (lane & 3) * 2;
    #pragma unroll
    for (int mt = 0; mt < 4; mt++) {
        #pragma unroll
        for (int nt = 0; nt < 8; nt++) {
            int col = wc * 64 + nt * 8 + qc;
            #pragma unroll
            for (int h = 0; h < 2; h++) {
                int row = wr * 64 + mt * 16 + h * 8 + qr;
                size_t o = obase + (size_t)row * EE + col;
                float2 xr = *(const float2*)(x + o);
                float2 r;
                r.x = acc[mt][nt][h*2 + 0] + xr.x;
                r.y = acc[mt][nt][h*2 + 1] + xr.y;
                *(float2*)(out + o) = r;
            }
        }
    }
}

// ============================================================
extern "C" void kernel_launch(void* const* d_in, const int* in_sizes, int n_in,
                              void* d_out, int out_size) {
    const float* x  = (const float*)d_in[0];   // [B, T, E] fp32
    const float* dp = (const float*)d_in[1];   // [CS, L] fp32
    float* out = (float*)d_out;

    const int SC_SMEM  = 2 * 65536 + 1024 + 64;    // 132160
    const int OUT_SMEM = 2 * 98304;                 // 196608
    cudaFuncSetAttribute(score_hmma_k, cudaFuncAttributeMaxDynamicSharedMemorySize, SC_SMEM);
    cudaFuncSetAttribute(out_hmma_k,   cudaFuncAttributeMaxDynamicSharedMemorySize, OUT_SMEM);

    normalize_k<<<(BB * TT) / 8, 256>>>(x);
    score_hmma_k<<<dim3(NCH, NCH, BB), 256, SC_SMEM>>>();
    topk_warp_k<<<dim3(NCH, BB), 32>>>();
    out_hmma_k<<<dim3(NCH, BB), 256, OUT_SMEM>>>(x, dp, out);
}

// round 12
// speedup vs baseline: 1.0487x; 1.0487x over previous
#include <cuda_runtime.h>
#include <cuda_bf16.h>
#include <math.h>
#include <stdint.h>

#define BB  2
#define TT  8192
#define EE  256
#define CSZ 128
#define NCH 64      // TT / CSZ
#define KT  8       // K slots (7 retrieved + current)

// ---- scratch (device globals; no allocation allowed) ----
__device__ __nv_bfloat16 g_hi[(size_t)BB * TT * EE];   // bf16 hi of normalized rows
__device__ __nv_bfloat16 g_lo[(size_t)BB * TT * EE];   // bf16 residual (normalized)
__device__ __nv_bfloat16 g_xh[(size_t)BB * TT * EE];   // bf16 hi of raw x
__device__ __nv_bfloat16 g_xl[(size_t)BB * TT * EE];   // bf16 residual of raw x
__device__ float g_scores[BB * NCH * NCH];
__device__ int   g_src[BB * NCH * KT];
__device__ float g_wgt[BB * NCH * KT];

// ================= helpers =================
__device__ __forceinline__ uint32_t smem_u32(const void* p) {
    uint32_t a;
    asm("{ .reg .u64 t; cvta.to.shared.u64 t, %1; cvt.u32.u64 %0, t; }" : "=r"(a) : "l"(p));
    return a;
}
__device__ __forceinline__ void cp_async16(uint32_t dst, const void* src) {
    asm volatile("cp.async.cg.shared.global [%0], [%1], 16;" :: "r"(dst), "l"(src));
}
#define CP_ASYNC_COMMIT() asm volatile("cp.async.commit_group;" ::: "memory")
#define CP_ASYNC_WAIT0()  asm volatile("cp.async.wait_group 0;"  ::: "memory")
#define LDSM_X4(R, a) \
    asm volatile("ldmatrix.sync.aligned.m8n8.x4.shared.b16 {%0,%1,%2,%3}, [%4];" \
        : "=r"((R)[0]), "=r"((R)[1]), "=r"((R)[2]), "=r"((R)[3]) : "r"(a))
#define LDSM_X4_T(R, a) \
    asm volatile("ldmatrix.sync.aligned.m8n8.x4.trans.shared.b16 {%0,%1,%2,%3}, [%4];" \
        : "=r"((R)[0]), "=r"((R)[1]), "=r"((R)[2]), "=r"((R)[3]) : "r"(a))
#define MMA16816(D, A, B0, B1) \
    asm volatile("mma.sync.aligned.m16n8k16.row.col.f32.bf16.bf16.f32 " \
        "{%0,%1,%2,%3}, {%4,%5,%6,%7}, {%8,%9}, {%0,%1,%2,%3};" \
        : "+f"((D)[0]), "+f"((D)[1]), "+f"((D)[2]), "+f"((D)[3]) \
        : "r"((A)[0]), "r"((A)[1]), "r"((A)[2]), "r"((A)[3]), "r"(B0), "r"(B1))

// ============================================================
// 1) Row normalization -> bf16 hi/lo of cn, plus bf16 hi/lo of raw x
// ============================================================
__global__ void normalize_k(const float* __restrict__ x) {
    int row  = blockIdx.x * 8 + (threadIdx.x >> 5);
    int lane = threadIdx.x & 31;
    const float4* xr = (const float4*)(x + (size_t)row * EE);
    float4 v0 = xr[lane];
    float4 v1 = xr[lane + 32];
    float ss = v0.x*v0.x + v0.y*v0.y + v0.z*v0.z + v0.w*v0.w
             + v1.x*v1.x + v1.y*v1.y + v1.z*v1.z + v1.w*v1.w;
    #pragma unroll
    for (int o = 16; o > 0; o >>= 1) ss += __shfl_xor_sync(0xffffffffu, ss, o);
    float inv = 1.0f / (sqrtf(ss) + 1e-6f);

    float fr[8] = { v0.x, v0.y, v0.z, v0.w, v1.x, v1.y, v1.z, v1.w };
    size_t base = (size_t)row * EE;
    uint32_t* hp = (uint32_t*)(g_hi + base);
    uint32_t* lp = (uint32_t*)(g_lo + base);
    uint32_t* xhp = (uint32_t*)(g_xh + base);
    uint32_t* xlp = (uint32_t*)(g_xl + base);

    __nv_bfloat16 h[8], l[8], rh[8], rl[8];
    #pragma unroll
    for (int t = 0; t < 8; t++) {
        float fn = fr[t] * inv;
        h[t]  = __float2bfloat16(fn);
        l[t]  = __float2bfloat16(fn - __bfloat162float(h[t]));
        rh[t] = __float2bfloat16(fr[t]);
        rl[t] = __float2bfloat16(fr[t] - __bfloat162float(rh[t]));
    }
    #pragma unroll
    for (int t = 0; t < 2; t++) {
        int eb = t * 64 + lane * 2;
        __nv_bfloat162 a0(h[t*4+0], h[t*4+1]),  a1(h[t*4+2], h[t*4+3]);
        __nv_bfloat162 b0(l[t*4+0], l[t*4+1]),  b1(l[t*4+2], l[t*4+3]);
        __nv_bfloat162 c0(rh[t*4+0], rh[t*4+1]), c1(rh[t*4+2], rh[t*4+3]);
        __nv_bfloat162 d0(rl[t*4+0], rl[t*4+1]), d1(rl[t*4+2], rl[t*4+3]);
        hp[eb]  = *(uint32_t*)&a0;  hp[eb+1]  = *(uint32_t*)&a1;
        lp[eb]  = *(uint32_t*)&b0;  lp[eb+1]  = *(uint32_t*)&b1;
        xhp[eb] = *(uint32_t*)&c0;  xhp[eb+1] = *(uint32_t*)&c1;
        xlp[eb] = *(uint32_t*)&d0;  xlp[eb+1] = *(uint32_t*)&d1;
    }
}

// ============================================================
// 2) Score kernel via mma.sync bf16x3 (R9 version — occ 2, validated)
// ============================================================
__global__ void __launch_bounds__(256, 2)
score_hmma_k() {
    int j = blockIdx.x, i = blockIdx.y, b = blockIdx.z;
    if (j >= i) return;

    extern __shared__ char smem[];
    uint32_t sb = smem_u32(smem);
    const uint32_t TSZ = 16384;
    float* red  = (float*)(smem + 4 * TSZ);
    float* wsum = (float*)(smem + 4 * TSZ + 1024);

    int tid  = threadIdx.x;
    int wid  = tid >> 5;
    int lane = tid & 31;
    int wr = wid >> 1;
    int wc = wid & 1;

    const __nv_bfloat16* srcp[4] = {
        g_hi + ((size_t)(b * NCH + i) * CSZ) * EE,
        g_lo + ((size_t)(b * NCH + i) * CSZ) * EE,
        g_hi + ((size_t)(b * NCH + j) * CSZ) * EE,
        g_lo + ((size_t)(b * NCH + j) * CSZ) * EE
    };

    float acc[2][8][4];
    #pragma unroll
    for (int mt = 0; mt < 2; mt++)
        #pragma unroll
        for (int nt = 0; nt < 8; nt++)
            #pragma unroll
            for (int e = 0; e < 4; e++) acc[mt][nt][e] = 0.0f;

    int a_r = (lane & 15);
    int a_c = (lane >> 4);
    int b_r = (lane & 7) + ((lane >> 4) << 3);
    int b_c = (lane >> 3) & 1;

    for (int c = 0; c < 4; c++) {
        int k0 = c * 64;
        #pragma unroll
        for (int t = 0; t < 4; t++) {
            const __nv_bfloat16* s = srcp[t] + k0;
            char* tb = smem + t * TSZ;
            #pragma unroll
            for (int q = 0; q < 4; q++) {
                int idx = q * 256 + tid;
                int r   = idx >> 3;
                int c8  = idx & 7;
                uint4 v = *(const uint4*)(s + (size_t)r * EE + c8 * 8);
                *(uint4*)(tb + r * 128 + ((c8 ^ (r & 7)) << 4)) = v;
            }
        }
        __syncthreads();

        #pragma unroll
        for (int kk = 0; kk < 4; kk++) {
            uint32_t ahi[2][4], alo[2][4];
            #pragma unroll
            for (int mt = 0; mt < 2; mt++) {
                int r   = wr * 32 + mt * 16 + a_r;
                int c16 = kk * 2 + a_c;
                uint32_t off = (uint32_t)(r * 128 + ((c16 ^ (r & 7)) << 4));
                LDSM_X4(ahi[mt], sb + 0 * TSZ + off);
                LDSM_X4(alo[mt], sb + 1 * TSZ + off);
            }
            #pragma unroll
            for (int np = 0; np < 4; np++) {
                int r   = wc * 64 + np * 16 + b_r;
                int c16 = kk * 2 + b_c;
                uint32_t off = (uint32_t)(r * 128 + ((c16 ^ (r & 7)) << 4));
                uint32_t bh[4], bl[4];
                LDSM_X4(bh, sb + 2 * TSZ + off);
                LDSM_X4(bl, sb + 3 * TSZ + off);
                #pragma unroll
                for (int mt = 0; mt < 2; mt++) {
                    #pragma unroll
                    for (int h = 0; h < 2; h++) {
                        float* D = acc[mt][np * 2 + h];
                        MMA16816(D, ahi[mt], bh[h*2], bh[h*2+1]);
                        MMA16816(D, ahi[mt], bl[h*2], bl[h*2+1]);
                        MMA16816(D, alo[mt], bh[h*2], bh[h*2+1]);
                    }
                }
            }
        }
        __syncthreads();
    }

    float mx[4];
    #pragma unroll
    for (int mt = 0; mt < 2; mt++) {
        float m0 = -3.0e38f, m1 = -3.0e38f;
        #pragma unroll
        for (int nt = 0; nt < 8; nt++) {
            m0 = fmaxf(m0, fmaxf(acc[mt][nt][0], acc[mt][nt][1]));
            m1 = fmaxf(m1, fmaxf(acc[mt][nt][2], acc[mt][nt][3]));
        }
        mx[mt * 2 + 0] = m0;
        mx[mt * 2 + 1] = m1;
    }
    #pragma unroll
    for (int o = 1; o <= 2; o <<= 1) {
        #pragma unroll
        for (int s = 0; s < 4; s++)
            mx[s] = fmaxf(mx[s], __shfl_xor_sync(0xffffffffu, mx[s], o));
    }
    if ((lane & 3) == 0) {
        int r = lane >> 2;
        #pragma unroll
        for (int s = 0; s < 4; s++) {
            int row = wr * 32 + (s >> 1) * 16 + (s & 1) * 8 + r;
            red[row * 2 + wc] = mx[s];
        }
    }
    __syncthreads();

    float total = 0.0f;
    if (tid < 128)
        total = fmaxf(red[tid * 2], red[tid * 2 + 1]);
    #pragma unroll
    for (int o = 16; o > 0; o >>= 1) total += __shfl_xor_sync(0xffffffffu, total, o);
    if (tid < 128 && lane == 0) wsum[wid] = total;
    __syncthreads();
    if (tid == 0)
        g_scores[(b * NCH + i) * NCH + j] = wsum[0] + wsum[1] + wsum[2] + wsum[3];
}

// ============================================================
// 3) Top-(K-1) selection, warp-parallel per (b,i).
// ============================================================
__global__ void topk_warp_k() {
    int i = blockIdx.x, b = blockIdx.y;
    int lane = threadIdx.x;
    const float* srow = g_scores + (b * NCH + i) * NCH;

    int num_sel = i < 7 ? i : 7;
    int shift   = 7 - num_sel;

    float v0 = (lane      < i) ? srow[lane]      : -3.0e38f;
    float v1 = (lane + 32 < i) ? srow[lane + 32] : -3.0e38f;

    float vals[7];
    int   idxs[7];
    for (int r = 0; r < num_sel; r++) {
        float mv = v0; int mi = lane;
        if (v1 > mv) { mv = v1; mi = lane + 32; }
        #pragma unroll
        for (int o = 16; o > 0; o >>= 1) {
            float ov = __shfl_xor_sync(0xffffffffu, mv, o);
            int   oi = __shfl_xor_sync(0xffffffffu, mi, o);
            if (ov > mv || (ov == mv && oi < mi)) { mv = ov; mi = oi; }
        }
        vals[r] = mv; idxs[r] = mi;
        if (mi == lane)      v0 = -3.0e38f;
        if (mi == lane + 32) v1 = -3.0e38f;
    }

    if (lane == 0) {
        float vmin = (num_sel > 0) ? vals[num_sel - 1] : 0.0f;
        int base = (b * NCH + i) * KT;
        for (int slot = 0; slot < 7; slot++) {
            if (slot >= shift) {
                int r = slot - shift;
                g_src[base + slot] = idxs[r];
                g_wgt[base + slot] = vals[r] / (vmin + 1e-6f);
            } else {
                g_src[base + slot] = i;
                g_wgt[base + slot] = 0.0f;
            }
        }
        g_src[base + 7] = i;
        g_wgt[base + 7] = 1.0f;
    }
}

// ============================================================
// 4) Output GEMM via mma.sync bf16x3.
//    TWO CTAs per (b,i): each computes C[128, 128] for e-half.
//    Warp tile 64x32 -> acc 64 regs -> occ 2 (16 warps/SM).
//    C = sum_s (w_s·dp[:, s*128:+128]) @ x[b,src_s][:, e-half] + x_chunk
// smem: AH 16K | AL 16K | BH 16K | BL 16K = 64KB
// ============================================================
__global__ void __launch_bounds__(256, 2)
out_hmma_k(const float* __restrict__ x, const float* __restrict__ dp,
           float* __restrict__ out) {
    int half = blockIdx.x, i = blockIdx.y, b = blockIdx.z;
    int e0 = half * 128;

    extern __shared__ char smem[];
    uint32_t sb = smem_u32(smem);
    const uint32_t AH = 0, AL = 16384, BH = 32768, BL = 49152;

    __shared__ int   s_src[KT];
    __shared__ float s_w[KT];

    int tid  = threadIdx.x;
    int wid  = tid >> 5;
    int lane = tid & 31;
    int wr = wid >> 2;      // 0..1 : rows [wr*64, +64)
    int wc = wid & 3;       // 0..3 : cols [wc*32, +32) within e-half

    if (tid < KT) {
        s_src[tid] = g_src[(b * NCH + i) * KT + tid];
        s_w[tid]   = g_wgt[(b * NCH + i) * KT + tid];
    }
    __syncthreads();

    float acc[4][4][4];   // mt(4 x m16) x nt(4 x n8) x frag4
    #pragma unroll
    for (int mt = 0; mt < 4; mt++)
        #pragma unroll
        for (int nt = 0; nt < 4; nt++)
            #pragma unroll
            for (int e = 0; e < 4; e++) acc[mt][nt][e] = 0.0f;

    int a_r = (lane & 15);
    int a_c = (lane >> 4);
    int b_k = (lane & 7) + (((lane >> 3) & 1) << 3);
    int b_g = (lane >> 4);

    for (int s = 0; s < KT; s++) {
        float w = s_w[s];
        if (w == 0.0f) continue;
        int src = s_src[s];

        for (int kc = 0; kc < 2; kc++) {
            // ---- B tiles via cp.async: 64 k-rows x 128 e (bf16 hi/lo) ----
            {
                size_t rb = ((size_t)b * TT + (size_t)src * CSZ + kc * 64) * EE + e0;
                const __nv_bfloat16* xbh = g_xh + rb;
                const __nv_bfloat16* xbl = g_xl + rb;
                #pragma unroll
                for (int q = 0; q < 4; q++) {
                    int idx = q * 256 + tid;   // 0..1023 granules
                    int k   = idx >> 4;        // k row 0..63
                    int g   = idx & 15;        // e granule 0..15
                    uint32_t dst = (uint32_t)(k * 256 + ((g ^ (k & 7)) << 4));
                    cp_async16(sb + BH + dst, xbh + (size_t)k * EE + g * 8);
                    cp_async16(sb + BL + dst, xbl + (size_t)k * EE + g * 8);
                }
                CP_ASYNC_COMMIT();
            }
            // ---- A tile: w * dp[c][s*128 + kc*64 + k], 128 rows x 64 cols ----
            {
                int col0 = s * 128 + kc * 64;
                #pragma unroll
                for (int q = 0; q < 4; q++) {
                    int idx = q * 256 + tid;   // 0..1023 granules
                    int r   = idx >> 3;        // row c
                    int gk  = idx & 7;         // k granule
                    const float* dps = dp + (size_t)r * 1024 + col0 + gk * 8;
                    float4 u0 = *(const float4*)(dps);
                    float4 u1 = *(const float4*)(dps + 4);
                    float f[8] = { w*u0.x, w*u0.y, w*u0.z, w*u0.w,
                                   w*u1.x, w*u1.y, w*u1.z, w*u1.w };
                    __nv_bfloat16 h[8], l[8];
                    #pragma unroll
                    for (int t = 0; t < 8; t++) {
                        h[t] = __float2bfloat16(f[t]);
                        l[t] = __float2bfloat16(f[t] - __bfloat162float(h[t]));
                    }
                    __nv_bfloat162 hh[4] = { {h[0],h[1]}, {h[2],h[3]}, {h[4],h[5]}, {h[6],h[7]} };
                    __nv_bfloat162 ll[4] = { {l[0],l[1]}, {l[2],l[3]}, {l[4],l[5]}, {l[6],l[7]} };
                    uint32_t dst = (uint32_t)(r * 128 + ((gk ^ (r & 7)) << 4));
                    *(uint4*)(smem + AH + dst) = *(uint4*)hh;
                    *(uint4*)(smem + AL + dst) = *(uint4*)ll;
                }
            }
            CP_ASYNC_WAIT0();
            __syncthreads();

            #pragma unroll
            for (int kk = 0; kk < 4; kk++) {
                uint32_t ahi[4][4], alo[4][4];
                #pragma unroll
                for (int mt = 0; mt < 4; mt++) {
                    int r   = wr * 64 + mt * 16 + a_r;
                    int c16 = kk * 2 + a_c;
                    uint32_t off = (uint32_t)(r * 128 + ((c16 ^ (r & 7)) << 4));
                    LDSM_X4(ahi[mt], sb + AH + off);
                    LDSM_X4(alo[mt], sb + AL + off);
                }
                #pragma unroll
                for (int np = 0; np < 2; np++) {
                    int k = kk * 16 + b_k;
                    int g = (wc * 4 + np * 2) + b_g;
                    uint32_t off = (uint32_t)(k * 256 + ((g ^ (k & 7)) << 4));
                    uint32_t bh[4], bl[4];
                    LDSM_X4_T(bh, sb + BH + off);
                    LDSM_X4_T(bl, sb + BL + off);
                    #pragma unroll
                    for (int mt = 0; mt < 4; mt++) {
                        #pragma unroll
                        for (int h = 0; h < 2; h++) {
                            float* D = acc[mt][np * 2 + h];
                            MMA16816(D, ahi[mt], bh[h*2], bh[h*2+1]);
                            MMA16816(D, ahi[mt], bl[h*2], bl[h*2+1]);
                            MMA16816(D, alo[mt], bh[h*2], bh[h*2+1]);
                        }
                    }
                }
            }
            __syncthreads();
        }
    }

    // ---- epilogue: += residual x chunk, store ----
    size_t obase = ((size_t)b * TT + (size_t)i * CSZ) * EE + e0;
    int qr = lane >> 2, qc = (lane & 3) * 2;
    #pragma unroll
    for (int mt = 0; mt < 4; mt++) {
        #pragma unroll
        for (int nt = 0; nt < 4; nt++) {
            int col = wc * 32 + nt * 8 + qc;
            #pragma unroll
            for (int h = 0; h < 2; h++) {
                int row = wr * 64 + mt * 16 + h * 8 + qr;
                size_t o = obase + (size_t)row * EE + col;
                float2 xr = *(const float2*)(x + o);
                float2 r;
                r.x = acc[mt][nt][h*2 + 0] + xr.x;
                r.y = acc[mt][nt][h*2 + 1] + xr.y;
                *(float2*)(out + o) = r;
            }
        }
    }
}

// ============================================================
extern "C" void kernel_launch(void* const* d_in, const int* in_sizes, int n_in,
                              void* d_out, int out_size) {
    const float* x  = (const float*)d_in[0];   // [B, T, E] fp32
    const float* dp = (const float*)d_in[1];   // [CS, L] fp32
    float* out = (float*)d_out;

    const int SC_SMEM  = 4 * 16384 + 1024 + 64;
    const int OUT_SMEM = 64 * 1024;
    cudaFuncSetAttribute(score_hmma_k, cudaFuncAttributeMaxDynamicSharedMemorySize, SC_SMEM);
    cudaFuncSetAttribute(out_hmma_k,   cudaFuncAttributeMaxDynamicSharedMemorySize, OUT_SMEM);

    normalize_k<<<(BB * TT) / 8, 256>>>(x);
    score_hmma_k<<<dim3(NCH, NCH, BB), 256, SC_SMEM>>>();
    topk_warp_k<<<dim3(NCH, BB), 32>>>();
    out_hmma_k<<<dim3(2, NCH, BB), 256, OUT_SMEM>>>(x, dp, out);
}